// round 6
// baseline (speedup 1.0000x reference)
#include <cuda_runtime.h>
#include <math.h>

#define TN 16000
#define NT 1024
#define NF 36
#define NB 64
#define NOUT 250
#define DH 128
#define NTAPS 257
#define KPHI 569
#define NCH 37

// ---------------- static device scratch ----------------
__device__ float2 d_X[NB * TN];        // scrambled forward FFT of x (8 MB, L2-resident)
__device__ float  d_psiw[NF * TN];     // psi_hat (scrambled order) / TN
__device__ float  d_phiw[NTAPS];       // time-domain lowpass taps
__device__ float2 d_rtA[128];          // W_16000^{-125 i}
__device__ float2 d_rtB[125];          // W_16000^{-i}
__device__ float  d_S1[NB * NCH * NOUT];

// ---------------- complex helpers ----------------
__device__ __forceinline__ float2 cmul(float2 a, float2 b) {
    return make_float2(a.x*b.x - a.y*b.y, a.x*b.y + a.y*b.x);
}
__device__ __forceinline__ float2 cadd(float2 a, float2 b){ return make_float2(a.x+b.x, a.y+b.y); }
__device__ __forceinline__ float2 csub(float2 a, float2 b){ return make_float2(a.x-b.x, a.y-b.y); }

// ---------------- prep kernels ----------------
__global__ void prep_phi() {
    int tap  = blockIdx.x;
    int lane = threadIdx.x;
    int d = tap - DH;
    const double sp = 0.35 / 64.0;
    const double PI2 = 6.283185307179586476925286766559;
    double acc = 0.0;
    for (int k = 1 + lane; k <= KPHI; k += 32) {
        double f = (double)k / (double)TN;
        double g = exp(-f*f / (2.0*sp*sp));
        acc += g * cos(PI2 * (double)k * (double)d / (double)TN);
    }
    for (int o = 16; o; o >>= 1) acc += __shfl_down_sync(0xffffffffu, acc, o);
    if (lane == 0) d_phiw[tap] = (float)((1.0 + 2.0*acc) / (double)TN);
}

__global__ void prep_tw() {
    int i = threadIdx.x;
    if (i < 128) { double s, c; sincospi(-(double)i/64.0,   &s, &c); d_rtA[i] = make_float2((float)c, (float)s); }
    if (i < 125) { double s, c; sincospi(-(double)i/8000.0, &s, &c); d_rtB[i] = make_float2((float)c, (float)s); }
}

__global__ void prep_psi() {
    int p = blockIdx.x * blockDim.x + threadIdx.x;
    if (p >= TN) return;
    // digit reversal for DIF radices [4,4,10,10,10] (position p -> frequency k)
    int k = (p/4000) + 4*((p/1000)%4) + 16*((p/100)%10) + 160*((p/10)%10) + 1600*(p%10);
    double f = (k < TN/2) ? (double)k / (double)TN : (double)(k - TN) / (double)TN;
    const double r   = pow(2.0, 1.0/6.0);
    const double fac = (r - 1.0) / (r + 1.0);
    #pragma unroll 1
    for (int j = 0; j < NF; ++j) {
        double xi = 0.35 * pow(2.0, -(double)j/6.0);
        double sg = xi * fac;
        double u  = (f - xi) / sg;
        double v  = (u*u < 400.0) ? exp(-0.5*u*u) : 0.0;
        d_psiw[j*TN + p] = (float)(v / (double)TN);
    }
}

// ---------------- small DFTs (SIGN = -1 forward, +1 inverse) ----------------
template<int SIGN>
__device__ __forceinline__ void dft4(float2&z0,float2&z1,float2&z2,float2&z3){
    float2 t0=cadd(z0,z2), t1=csub(z0,z2), t2=cadd(z1,z3), t3=csub(z1,z3);
    const float s = (float)SIGN;
    z0 = cadd(t0,t2);
    z2 = csub(t0,t2);
    z1 = make_float2(t1.x - s*t3.y, t1.y + s*t3.x);
    z3 = make_float2(t1.x + s*t3.y, t1.y - s*t3.x);
}

template<int SIGN>
__device__ __forceinline__ void dft5(float2&z0,float2&z1,float2&z2,float2&z3,float2&z4){
    const float K1 =  0.309016994374947424f;
    const float K2 = -0.809016994374947424f;
    const float S1 =  0.951056516295153572f;
    const float S2 =  0.587785252292473129f;
    float2 t1=cadd(z1,z4), t2=cadd(z2,z3), t3=csub(z1,z4), t4=csub(z2,z3);
    float2 a = z0;
    float2 sum = cadd(a, cadd(t1,t2));
    float2 r1 = make_float2(a.x + K1*t1.x + K2*t2.x, a.y + K1*t1.y + K2*t2.y);
    float2 r2 = make_float2(a.x + K2*t1.x + K1*t2.x, a.y + K2*t1.y + K1*t2.y);
    float2 q1 = make_float2(S1*t3.x + S2*t4.x, S1*t3.y + S2*t4.y);
    float2 q2 = make_float2(S2*t3.x - S1*t4.x, S2*t3.y - S1*t4.y);
    const float s = (float)SIGN;
    z0 = sum;
    z1 = make_float2(r1.x - s*q1.y, r1.y + s*q1.x);
    z4 = make_float2(r1.x + s*q1.y, r1.y - s*q1.x);
    z2 = make_float2(r2.x - s*q2.y, r2.y + s*q2.x);
    z3 = make_float2(r2.x + s*q2.y, r2.y - s*q2.x);
}

// twiddle W_16000^{-x}, x in [0,16000): x = 125a + b
__device__ __forceinline__ float2 twb(int x, const float2* rtA, const float2* rtB){
    int a = x / 125;
    return cmul(rtA[a], rtB[x - a*125]);
}

// ---------------- fused radix-16 (= radix-4 M=4000, radix-4 M=1000), subN=16000 ----------------
// forward first stage: reads real xs, writes buf
__device__ void stage16_fwd(float2* buf, const float* xs, const float2* rtA, const float2* rtB){
    const float2 c16_1 = make_float2(0.92387953251128674f, -0.38268343236508977f);
    const float2 c16_2 = make_float2(0.70710678118654752f, -0.70710678118654752f);
    const float2 c16_3 = make_float2(0.38268343236508977f, -0.92387953251128674f);
    for (int p = threadIdx.x; p < 1000; p += NT) {
        float2 z[16];
        #pragma unroll
        for (int j=0;j<4;j++)
            #pragma unroll
            for (int i=0;i<4;i++)
                z[4*j+i] = make_float2(xs[p + 1000*j + 4000*i], 0.f);
        float2 a = twb(p, rtA, rtB);
        float2 b = twb(4*p, rtA, rtB);
        #pragma unroll
        for (int j=0;j<4;j++) dft4<-1>(z[4*j+0], z[4*j+1], z[4*j+2], z[4*j+3]);   // over i -> s1
        #pragma unroll
        for (int j=0;j<4;j++){
            float2 t = (j==0)? a : (j==1? cmul(a,c16_1) : (j==2? cmul(a,c16_2) : cmul(a,c16_3)));
            float2 t2 = cmul(t,t);
            z[4*j+1]=cmul(z[4*j+1],t); z[4*j+2]=cmul(z[4*j+2],t2); z[4*j+3]=cmul(z[4*j+3],cmul(t2,t));
        }
        #pragma unroll
        for (int s1=0;s1<4;s1++) dft4<-1>(z[s1], z[4+s1], z[8+s1], z[12+s1]);     // over j -> s2
        float2 b2 = cmul(b,b), b3 = cmul(b2,b);
        #pragma unroll
        for (int s1=0;s1<4;s1++){ z[4+s1]=cmul(z[4+s1],b); z[8+s1]=cmul(z[8+s1],b2); z[12+s1]=cmul(z[12+s1],b3); }
        #pragma unroll
        for (int s1=0;s1<4;s1++)
            #pragma unroll
            for (int s2=0;s2<4;s2++)
                buf[s1*4000 + s2*1000 + p] = z[4*s2+s1];
    }
    __syncthreads();
}

// inverse last stage: reads buf, writes U = |z| (natural time order)
__device__ void stage16_inv_abs(const float2* buf, float* U, const float2* rtA, const float2* rtB){
    const float2 c16_1 = make_float2(0.92387953251128674f,  0.38268343236508977f);
    const float2 c16_2 = make_float2(0.70710678118654752f,  0.70710678118654752f);
    const float2 c16_3 = make_float2(0.38268343236508977f,  0.92387953251128674f);
    for (int p = threadIdx.x; p < 1000; p += NT) {
        float2 z[16];
        #pragma unroll
        for (int s1=0;s1<4;s1++)
            #pragma unroll
            for (int s2=0;s2<4;s2++)
                z[4*s2+s1] = buf[s1*4000 + s2*1000 + p];
        float2 a = twb(p, rtA, rtB);   a.y = -a.y;
        float2 b = twb(4*p, rtA, rtB); b.y = -b.y;
        float2 b2 = cmul(b,b), b3 = cmul(b2,b);
        #pragma unroll
        for (int s1=0;s1<4;s1++){ z[4+s1]=cmul(z[4+s1],b); z[8+s1]=cmul(z[8+s1],b2); z[12+s1]=cmul(z[12+s1],b3); }
        #pragma unroll
        for (int s1=0;s1<4;s1++) dft4<1>(z[s1], z[4+s1], z[8+s1], z[12+s1]);      // over s2 -> j
        #pragma unroll
        for (int j=0;j<4;j++){
            float2 t = (j==0)? a : (j==1? cmul(a,c16_1) : (j==2? cmul(a,c16_2) : cmul(a,c16_3)));
            float2 t2 = cmul(t,t);
            z[4*j+1]=cmul(z[4*j+1],t); z[4*j+2]=cmul(z[4*j+2],t2); z[4*j+3]=cmul(z[4*j+3],cmul(t2,t));
        }
        #pragma unroll
        for (int j=0;j<4;j++) dft4<1>(z[4*j+0], z[4*j+1], z[4*j+2], z[4*j+3]);    // over s1 -> i
        #pragma unroll
        for (int j=0;j<4;j++)
            #pragma unroll
            for (int i=0;i<4;i++){
                float2 v = z[4*j+i];
                U[p + 1000*j + 4000*i] = sqrtf(v.x*v.x + v.y*v.y);
            }
    }
    __syncthreads();
}

// ---------------- fused radix-10 (= 2x5) middle stages; CC = 16000/subN ----------------
template<int M, int CC, int SIGN>
__device__ void stage10(float2* buf, const float2* rtA, const float2* rtB){
    const float c1x=0.809016994374947424f, c1y=0.587785252292473129f;
    const float c2x=0.309016994374947424f, c2y=0.951056516295153572f;
    const float sg = (SIGN<0)? 1.f : -1.f;
    const float2 w10_1 = make_float2( c1x, -sg*c1y);
    const float2 w10_2 = make_float2( c2x, -sg*c2y);
    const float2 w10_3 = make_float2(-c2x, -sg*c2y);
    const float2 w10_4 = make_float2(-c1x, -sg*c1y);
    for (int idx = threadIdx.x; idx < 1600; idx += NT) {
        int blk = idx / M;
        int p   = idx - blk*M;
        int o   = blk*(10*M) + p;
        float2 z[10];
        #pragma unroll
        for (int i=0;i<10;i++) z[i] = buf[o + M*i];
        float2 v = twb(CC*p, rtA, rtB);
        if (SIGN > 0) v.y = -v.y;
        float2 b  = cmul(v,v);
        float2 b2 = cmul(b,b);
        float2 b3 = cmul(b2,b);
        float2 b4 = cmul(b2,b2);
        float2 m1 = cmul(w10_1, v);
        float2 m2 = cmul(w10_2, v);
        float2 m3 = cmul(w10_3, v);
        float2 m4 = cmul(w10_4, v);
        if (SIGN < 0) {
            float2 e0=cadd(z[0],z[5]), e1=cadd(z[1],z[6]), e2=cadd(z[2],z[7]), e3=cadd(z[3],z[8]), e4=cadd(z[4],z[9]);
            float2 q0=cmul(csub(z[0],z[5]), v ), q1=cmul(csub(z[1],z[6]), m1),
                   q2=cmul(csub(z[2],z[7]), m2), q3=cmul(csub(z[3],z[8]), m3),
                   q4=cmul(csub(z[4],z[9]), m4);
            dft5<-1>(e0,e1,e2,e3,e4);
            dft5<-1>(q0,q1,q2,q3,q4);
            z[0]=e0;          z[1]=q0;
            z[2]=cmul(e1,b);  z[3]=cmul(q1,b);
            z[4]=cmul(e2,b2); z[5]=cmul(q2,b2);
            z[6]=cmul(e3,b3); z[7]=cmul(q3,b3);
            z[8]=cmul(e4,b4); z[9]=cmul(q4,b4);
        } else {
            float2 E0=z[0], E1=cmul(z[2],b), E2=cmul(z[4],b2), E3=cmul(z[6],b3), E4=cmul(z[8],b4);
            float2 O0=z[1], O1=cmul(z[3],b), O2=cmul(z[5],b2), O3=cmul(z[7],b3), O4=cmul(z[9],b4);
            dft5<1>(E0,E1,E2,E3,E4);
            dft5<1>(O0,O1,O2,O3,O4);
            O0=cmul(O0,v ); O1=cmul(O1,m1); O2=cmul(O2,m2); O3=cmul(O3,m3); O4=cmul(O4,m4);
            z[0]=cadd(E0,O0); z[5]=csub(E0,O0);
            z[1]=cadd(E1,O1); z[6]=csub(E1,O1);
            z[2]=cadd(E2,O2); z[7]=csub(E2,O2);
            z[3]=cadd(E3,O3); z[8]=csub(E3,O3);
            z[4]=cadd(E4,O4); z[9]=csub(E4,O4);
        }
        #pragma unroll
        for (int i=0;i<10;i++) buf[o + M*i] = z[i];
    }
    __syncthreads();
}

// forward last stage: radix-10 M=1, no twiddle, store natural to global X (vectorized)
__device__ void stage10_fwd_store(const float2* buf, float2* __restrict__ Xo){
    const float c1x=0.809016994374947424f, c1y=0.587785252292473129f;
    const float c2x=0.309016994374947424f, c2y=0.951056516295153572f;
    const float2 w1 = make_float2( c1x, -c1y);
    const float2 w2 = make_float2( c2x, -c2y);
    const float2 w3 = make_float2(-c2x, -c2y);
    const float2 w4 = make_float2(-c1x, -c1y);
    for (int blk = threadIdx.x; blk < 1600; blk += NT) {
        int o = 10*blk;
        float2 z[10];
        #pragma unroll
        for (int i=0;i<10;i++) z[i] = buf[o+i];
        float2 e0=cadd(z[0],z[5]), e1=cadd(z[1],z[6]), e2=cadd(z[2],z[7]), e3=cadd(z[3],z[8]), e4=cadd(z[4],z[9]);
        float2 q0=csub(z[0],z[5]),           q1=cmul(csub(z[1],z[6]), w1),
               q2=cmul(csub(z[2],z[7]), w2), q3=cmul(csub(z[3],z[8]), w3),
               q4=cmul(csub(z[4],z[9]), w4);
        dft5<-1>(e0,e1,e2,e3,e4);
        dft5<-1>(q0,q1,q2,q3,q4);
        float4* X4 = (float4*)(Xo + o);
        X4[0] = make_float4(e0.x,e0.y,q0.x,q0.y);
        X4[1] = make_float4(e1.x,e1.y,q1.x,q1.y);
        X4[2] = make_float4(e2.x,e2.y,q2.x,q2.y);
        X4[3] = make_float4(e3.x,e3.y,q3.x,q3.y);
        X4[4] = make_float4(e4.x,e4.y,q4.x,q4.y);
    }
}

// inverse first stage: radix-10 M=1, no twiddle, reads global X * psi (vectorized)
__device__ void stage10_inv_load(float2* buf, const float2* __restrict__ Xb, const float* __restrict__ pw){
    const float c1x=0.809016994374947424f, c1y=0.587785252292473129f;
    const float c2x=0.309016994374947424f, c2y=0.951056516295153572f;
    const float2 w1 = make_float2( c1x,  c1y);
    const float2 w2 = make_float2( c2x,  c2y);
    const float2 w3 = make_float2(-c2x,  c2y);
    const float2 w4 = make_float2(-c1x,  c1y);
    for (int blk = threadIdx.x; blk < 1600; blk += NT) {
        int o = 10*blk;
        const float4* X4 = (const float4*)(Xb + o);
        const float2* P2 = (const float2*)(pw + o);
        float2 z[10];
        #pragma unroll
        for (int i=0;i<5;i++){
            float4 xv = X4[i];
            float2 wv = P2[i];
            z[2*i]   = make_float2(xv.x*wv.x, xv.y*wv.x);
            z[2*i+1] = make_float2(xv.z*wv.y, xv.w*wv.y);
        }
        float2 E0=z[0], E1=z[2], E2=z[4], E3=z[6], E4=z[8];
        float2 O0=z[1], O1=z[3], O2=z[5], O3=z[7], O4=z[9];
        dft5<1>(E0,E1,E2,E3,E4);
        dft5<1>(O0,O1,O2,O3,O4);
        O1=cmul(O1,w1); O2=cmul(O2,w2); O3=cmul(O3,w3); O4=cmul(O4,w4);
        buf[o  ]=cadd(E0,O0); buf[o+5]=csub(E0,O0);
        buf[o+1]=cadd(E1,O1); buf[o+6]=csub(E1,O1);
        buf[o+2]=cadd(E2,O2); buf[o+7]=csub(E2,O2);
        buf[o+3]=cadd(E3,O3); buf[o+8]=csub(E3,O3);
        buf[o+4]=cadd(E4,O4); buf[o+9]=csub(E4,O4);
    }
    __syncthreads();
}

__device__ void init_tables(float2* rtA, float2* rtB, float* sphi){
    for (int i = threadIdx.x; i < 128; i += NT) rtA[i] = d_rtA[i];
    for (int i = threadIdx.x; i < 125; i += NT) rtB[i] = d_rtB[i];
    for (int i = threadIdx.x; i < NTAPS; i += NT) sphi[i] = d_phiw[i];
}

// warp-per-output smoothing: conflict-free coalesced LDS, shuffle reduce
__device__ void smooth(const float* __restrict__ S, const float* __restrict__ sphi, float* dst){
    int w = threadIdx.x >> 5, l = threadIdx.x & 31;
    for (int m0 = w; m0 < NOUT; m0 += NT/32) {
        int center = 64*m0 + DH;
        float acc = 0.f;
        #pragma unroll
        for (int i = 0; i < (NTAPS-1)/32; ++i) {
            int id = center - l - 32*i;
            if (id >= TN) id -= TN;
            if (id < 0)   id += TN;
            acc += sphi[l + 32*i] * S[id];
        }
        if (l == 0) {
            int id = center - (NTAPS-1);
            if (id < 0) id += TN;
            acc += sphi[NTAPS-1] * S[id];
        }
        #pragma unroll
        for (int o = 16; o; o >>= 1) acc += __shfl_down_sync(0xffffffffu, acc, o);
        if (l == 0) dst[m0] = acc;
    }
}

// ---------------- kernel 1: forward FFT of x (+ S0) ----------------
__global__ __launch_bounds__(NT, 1) void k_fwd(const float* __restrict__ x){
    extern __shared__ __align__(16) unsigned char sm[];
    float2* buf = (float2*)sm;                       // 16000 complex
    float*  xs  = (float*)(sm + TN*sizeof(float2));  // 16000 real
    __shared__ float2 rtA[128]; __shared__ float2 rtB[125]; __shared__ float sphi[NTAPS];
    int b = blockIdx.x;
    init_tables(rtA, rtB, sphi);
    const float4* xb4 = (const float4*)(x + b*TN);
    float4* xs4 = (float4*)xs;
    for (int n = threadIdx.x; n < TN/4; n += NT) xs4[n] = xb4[n];
    __syncthreads();
    smooth(xs, sphi, &d_S1[(b*NCH + 0)*NOUT]);       // S0 in time domain
    stage16_fwd(buf, xs, rtA, rtB);
    stage10<100,16,-1>(buf, rtA, rtB);
    stage10<10,160,-1>(buf, rtA, rtB);
    stage10_fwd_store(buf, d_X + b*TN);
}

// ---------------- kernel 2: band-pass ifft + |.| + smoothing ----------------
__global__ __launch_bounds__(NT, 1) void k_band(){
    extern __shared__ __align__(16) unsigned char sm[];
    float2* buf = (float2*)sm;
    float*  U   = (float*)(sm + TN*sizeof(float2));
    __shared__ float2 rtA[128]; __shared__ float2 rtB[125]; __shared__ float sphi[NTAPS];
    int j = blockIdx.x, b = blockIdx.y;
    init_tables(rtA, rtB, sphi);
    __syncthreads();
    stage10_inv_load(buf, d_X + b*TN, d_psiw + j*TN);
    stage10<10,160,1>(buf, rtA, rtB);
    stage10<100,16,1>(buf, rtA, rtB);
    stage16_inv_abs(buf, U, rtA, rtB);
    smooth(U, sphi, &d_S1[(b*NCH + 1 + j)*NOUT]);
}

// ---------------- kernel 3: channel-group means ----------------
__global__ void k_reduce(float* __restrict__ out){
    int i = blockIdx.x * blockDim.x + threadIdx.x;
    if (i >= NB*3*NOUT) return;
    int m0 = i % NOUT;
    int g  = (i / NOUT) % 3;
    int b  = i / (3*NOUT);
    int c0 = (g==0) ? 0 : (g==1 ? 12 : 24);
    int nc = (g==2) ? 13 : 12;
    float acc = 0.f;
    for (int c = 0; c < nc; ++c) acc += d_S1[(b*NCH + c0 + c)*NOUT + m0];
    out[i] = acc / (float)nc;
}

// ---------------- launch ----------------
extern "C" void kernel_launch(void* const* d_in, const int* in_sizes, int n_in,
                              void* d_out, int out_size) {
    (void)in_sizes; (void)n_in; (void)out_size;
    const float* x = (const float*)d_in[0];
    float* out = (float*)d_out;
    const int smbytes = TN*(int)sizeof(float2) + TN*(int)sizeof(float);  // 192000
    cudaFuncSetAttribute(k_fwd,  cudaFuncAttributeMaxDynamicSharedMemorySize, smbytes);
    cudaFuncSetAttribute(k_band, cudaFuncAttributeMaxDynamicSharedMemorySize, smbytes);
    prep_phi<<<NTAPS, 32>>>();
    prep_tw<<<1, 128>>>();
    prep_psi<<<(TN + 255)/256, 256>>>();
    k_fwd<<<NB, NT, smbytes>>>(x);
    k_band<<<dim3(NF, NB), NT, smbytes>>>();
    k_reduce<<<(NB*3*NOUT + 255)/256, 256>>>(out);
}

// round 7
// speedup vs baseline: 1.8286x; 1.8286x over previous
#include <cuda_runtime.h>
#include <math.h>

#define TN 16000
#define NT 1024
#define NF 36
#define NB 64
#define NOUT 250
#define NTAPS 257
#define KPHI 569
#define NCH 37
#define TBL 146000

// ---------------- static device scratch ----------------
__device__ float2 d_X[NB * TN];        // scrambled forward FFT of x (8 MB, L2-resident)
__device__ int    d_idx[TBL];          // per-channel gather index into scrambled X
__device__ float  d_wt[TBL];           // per-channel psi_hat weight (incl 1/16000)
__device__ float  d_phiw[NTAPS];       // time-domain lowpass taps phi(d), d=-128..128
__device__ float2 d_rtA[128];          // W_16000^{-125 i}
__device__ float2 d_rtB[125];          // W_16000^{-i}
__device__ float  d_S1[NB * NCH * NOUT];

// ---------------- complex helpers ----------------
__device__ __forceinline__ float2 cmul(float2 a, float2 b) {
    return make_float2(a.x*b.x - a.y*b.y, a.x*b.y + a.y*b.x);
}
__device__ __forceinline__ float2 cadd(float2 a, float2 b){ return make_float2(a.x+b.x, a.y+b.y); }
__device__ __forceinline__ float2 csub(float2 a, float2 b){ return make_float2(a.x-b.x, a.y-b.y); }

// ---------------- prep kernels ----------------
__global__ void prep_phi() {
    int tap  = blockIdx.x;
    int lane = threadIdx.x;
    int d = tap - 128;
    const double sp = 0.35 / 64.0;
    const double PI2 = 6.283185307179586476925286766559;
    double acc = 0.0;
    for (int k = 1 + lane; k <= KPHI; k += 32) {
        double f = (double)k / (double)TN;
        double g = exp(-f*f / (2.0*sp*sp));
        acc += g * cos(PI2 * (double)k * (double)d / (double)TN);
    }
    for (int o = 16; o; o >>= 1) acc += __shfl_down_sync(0xffffffffu, acc, o);
    if (lane == 0) d_phiw[tap] = (float)((1.0 + 2.0*acc) / (double)TN);
}

__global__ void prep_tw() {
    int i = threadIdx.x;
    if (i < 128) { double s, c; sincospi(-(double)i/64.0,   &s, &c); d_rtA[i] = make_float2((float)c, (float)s); }
    if (i < 125) { double s, c; sincospi(-(double)i/8000.0, &s, &c); d_rtB[i] = make_float2((float)c, (float)s); }
}

// per-channel decimated gather tables
__global__ void prep_band() {
    int q = blockIdx.x * blockDim.x + threadIdx.x;
    int j = blockIdx.y;
    int cls, NJ, off;
    if      (j <  2){ cls=0; NJ=16000; off = j*16000; }
    else if (j <  9){ cls=1; NJ= 8000; off = 32000  + (j-2)*8000; }
    else if (j < 16){ cls=2; NJ= 4000; off = 88000  + (j-9)*4000; }
    else if (j < 26){ cls=3; NJ= 2000; off = 116000 + (j-16)*2000; }
    else            { cls=4; NJ= 1000; off = 136000 + (j-26)*1000; }
    if (q >= NJ) return;
    // digit reversal for the class's forward-DIF radix list -> natural frequency k
    int k;
    if (cls == 0) { int a=q/4000, b=(q/1000)%4, c=(q/100)%10, d=(q/10)%10, e=q%10; k = a + 4*b + 16*c + 160*d + 1600*e; }
    else if (cls == 1) { int a=q/4000, b=(q/1000)%4, c=(q/100)%10, d=(q/10)%10, e=q%10; k = a + 2*b + 8*c + 80*d + 800*e; }
    else if (cls == 2) { int b=q/1000, c=(q/100)%10, d=(q/10)%10, e=q%10; k = b + 4*c + 40*d + 400*e; }
    else if (cls == 3) { int a=q/1000, c=(q/100)%10, d=(q/10)%10, e=q%10; k = a + 2*c + 20*d + 200*e; }
    else               { int c=q/100, d=(q/10)%10, e=q%10; k = c + 10*d + 100*e; }
    // scrambled position of natural frequency k in the stored 16000 layout
    int e2 = k/1600, r = k - 1600*e2;
    int d2 = r/160;  r -= 160*d2;
    int c2 = r/16;   r -= 16*c2;
    int b2 = r/4,    a2 = r - 4*b2;
    int p = 4000*a2 + 1000*b2 + 100*c2 + 10*d2 + e2;
    // psi weight
    double f = (k < 8000) ? (double)k/(double)TN : (double)(k - TN)/(double)TN;
    const double rr  = pow(2.0, 1.0/6.0);
    const double fac = (rr - 1.0) / (rr + 1.0);
    double xi = 0.35 * pow(2.0, -(double)j/6.0);
    double sg = xi * fac;
    double u  = (f - xi) / sg;
    double v  = (u*u < 400.0) ? exp(-0.5*u*u) : 0.0;
    d_idx[off+q] = p;
    d_wt[off+q]  = (float)(v / (double)TN);
}

// ---------------- small DFTs ----------------
template<int SIGN>
__device__ __forceinline__ void dft4(float2&z0,float2&z1,float2&z2,float2&z3){
    float2 t0=cadd(z0,z2), t1=csub(z0,z2), t2=cadd(z1,z3), t3=csub(z1,z3);
    const float s = (float)SIGN;
    z0 = cadd(t0,t2);
    z2 = csub(t0,t2);
    z1 = make_float2(t1.x - s*t3.y, t1.y + s*t3.x);
    z3 = make_float2(t1.x + s*t3.y, t1.y - s*t3.x);
}

template<int SIGN>
__device__ __forceinline__ void dft5(float2&z0,float2&z1,float2&z2,float2&z3,float2&z4){
    const float K1 =  0.309016994374947424f;
    const float K2 = -0.809016994374947424f;
    const float S1 =  0.951056516295153572f;
    const float S2 =  0.587785252292473129f;
    float2 t1=cadd(z1,z4), t2=cadd(z2,z3), t3=csub(z1,z4), t4=csub(z2,z3);
    float2 a = z0;
    float2 sum = cadd(a, cadd(t1,t2));
    float2 r1 = make_float2(a.x + K1*t1.x + K2*t2.x, a.y + K1*t1.y + K2*t2.y);
    float2 r2 = make_float2(a.x + K2*t1.x + K1*t2.x, a.y + K2*t1.y + K1*t2.y);
    float2 q1 = make_float2(S1*t3.x + S2*t4.x, S1*t3.y + S2*t4.y);
    float2 q2 = make_float2(S2*t3.x - S1*t4.x, S2*t3.y - S1*t4.y);
    const float s = (float)SIGN;
    z0 = sum;
    z1 = make_float2(r1.x - s*q1.y, r1.y + s*q1.x);
    z4 = make_float2(r1.x + s*q1.y, r1.y - s*q1.x);
    z2 = make_float2(r2.x - s*q2.y, r2.y + s*q2.x);
    z3 = make_float2(r2.x + s*q2.y, r2.y - s*q2.x);
}

__device__ __forceinline__ float2 twb(int x, const float2* rtA, const float2* rtB){
    int a = x / 125;
    return cmul(rtA[a], rtB[x - a*125]);
}

// ================= forward-only pieces (k_fwd, size 16000, NT threads) =================
__device__ void stage16_fwd(float2* buf, const float* xs, const float2* rtA, const float2* rtB){
    const float2 c16_1 = make_float2(0.92387953251128674f, -0.38268343236508977f);
    const float2 c16_2 = make_float2(0.70710678118654752f, -0.70710678118654752f);
    const float2 c16_3 = make_float2(0.38268343236508977f, -0.92387953251128674f);
    for (int p = threadIdx.x; p < 1000; p += NT) {
        float2 z[16];
        #pragma unroll
        for (int j=0;j<4;j++)
            #pragma unroll
            for (int i=0;i<4;i++)
                z[4*j+i] = make_float2(xs[p + 1000*j + 4000*i], 0.f);
        float2 a = twb(p, rtA, rtB);
        float2 b = twb(4*p, rtA, rtB);
        #pragma unroll
        for (int j=0;j<4;j++) dft4<-1>(z[4*j+0], z[4*j+1], z[4*j+2], z[4*j+3]);
        #pragma unroll
        for (int j=0;j<4;j++){
            float2 t = (j==0)? a : (j==1? cmul(a,c16_1) : (j==2? cmul(a,c16_2) : cmul(a,c16_3)));
            float2 t2 = cmul(t,t);
            z[4*j+1]=cmul(z[4*j+1],t); z[4*j+2]=cmul(z[4*j+2],t2); z[4*j+3]=cmul(z[4*j+3],cmul(t2,t));
        }
        #pragma unroll
        for (int s1=0;s1<4;s1++) dft4<-1>(z[s1], z[4+s1], z[8+s1], z[12+s1]);
        float2 b2 = cmul(b,b), b3 = cmul(b2,b);
        #pragma unroll
        for (int s1=0;s1<4;s1++){ z[4+s1]=cmul(z[4+s1],b); z[8+s1]=cmul(z[8+s1],b2); z[12+s1]=cmul(z[12+s1],b3); }
        #pragma unroll
        for (int s1=0;s1<4;s1++)
            #pragma unroll
            for (int s2=0;s2<4;s2++)
                buf[s1*4000 + s2*1000 + p] = z[4*s2+s1];
    }
    __syncthreads();
}

template<int M, int CC>
__device__ void stage10_fwd(float2* buf, const float2* rtA, const float2* rtB){
    const float c1x=0.809016994374947424f, c1y=0.587785252292473129f;
    const float c2x=0.309016994374947424f, c2y=0.951056516295153572f;
    const float2 w10_1 = make_float2( c1x, -c1y);
    const float2 w10_2 = make_float2( c2x, -c2y);
    const float2 w10_3 = make_float2(-c2x, -c2y);
    const float2 w10_4 = make_float2(-c1x, -c1y);
    for (int idx = threadIdx.x; idx < 1600; idx += NT) {
        int blk = idx / M;
        int p   = idx - blk*M;
        int o   = blk*(10*M) + p;
        float2 z[10];
        #pragma unroll
        for (int i=0;i<10;i++) z[i] = buf[o + M*i];
        float2 v = twb(CC*p, rtA, rtB);
        float2 b  = cmul(v,v);
        float2 b2 = cmul(b,b);
        float2 b3 = cmul(b2,b);
        float2 b4 = cmul(b2,b2);
        float2 m1 = cmul(w10_1, v);
        float2 m2 = cmul(w10_2, v);
        float2 m3 = cmul(w10_3, v);
        float2 m4 = cmul(w10_4, v);
        float2 e0=cadd(z[0],z[5]), e1=cadd(z[1],z[6]), e2=cadd(z[2],z[7]), e3=cadd(z[3],z[8]), e4=cadd(z[4],z[9]);
        float2 q0=cmul(csub(z[0],z[5]), v ), q1=cmul(csub(z[1],z[6]), m1),
               q2=cmul(csub(z[2],z[7]), m2), q3=cmul(csub(z[3],z[8]), m3),
               q4=cmul(csub(z[4],z[9]), m4);
        dft5<-1>(e0,e1,e2,e3,e4);
        dft5<-1>(q0,q1,q2,q3,q4);
        z[0]=e0;          z[1]=q0;
        z[2]=cmul(e1,b);  z[3]=cmul(q1,b);
        z[4]=cmul(e2,b2); z[5]=cmul(q2,b2);
        z[6]=cmul(e3,b3); z[7]=cmul(q3,b3);
        z[8]=cmul(e4,b4); z[9]=cmul(q4,b4);
        #pragma unroll
        for (int i=0;i<10;i++) buf[o + M*i] = z[i];
    }
    __syncthreads();
}

__device__ void stage10_fwd_store(const float2* buf, float2* __restrict__ Xo){
    const float c1x=0.809016994374947424f, c1y=0.587785252292473129f;
    const float c2x=0.309016994374947424f, c2y=0.951056516295153572f;
    const float2 w1 = make_float2( c1x, -c1y);
    const float2 w2 = make_float2( c2x, -c2y);
    const float2 w3 = make_float2(-c2x, -c2y);
    const float2 w4 = make_float2(-c1x, -c1y);
    for (int blk = threadIdx.x; blk < 1600; blk += NT) {
        int o = 10*blk;
        float2 z[10];
        #pragma unroll
        for (int i=0;i<10;i++) z[i] = buf[o+i];
        float2 e0=cadd(z[0],z[5]), e1=cadd(z[1],z[6]), e2=cadd(z[2],z[7]), e3=cadd(z[3],z[8]), e4=cadd(z[4],z[9]);
        float2 q0=csub(z[0],z[5]),           q1=cmul(csub(z[1],z[6]), w1),
               q2=cmul(csub(z[2],z[7]), w2), q3=cmul(csub(z[3],z[8]), w3),
               q4=cmul(csub(z[4],z[9]), w4);
        dft5<-1>(e0,e1,e2,e3,e4);
        dft5<-1>(q0,q1,q2,q3,q4);
        float4* X4 = (float4*)(Xo + o);
        X4[0] = make_float4(e0.x,e0.y,q0.x,q0.y);
        X4[1] = make_float4(e1.x,e1.y,q1.x,q1.y);
        X4[2] = make_float4(e2.x,e2.y,q2.x,q2.y);
        X4[3] = make_float4(e3.x,e3.y,q3.x,q3.y);
        X4[4] = make_float4(e4.x,e4.y,q4.x,q4.y);
    }
}

// ================= inverse pieces (generic over size / thread count) =================

// first DIT stage (radix-10, M=1, no twiddle): gather X via idx/wt tables
template<int THR>
__device__ void s10_load(float2* buf, const float2* __restrict__ Xb,
                         const int* __restrict__ idx, const float* __restrict__ wt, int cnt10){
    const float c1x=0.809016994374947424f, c1y=0.587785252292473129f;
    const float c2x=0.309016994374947424f, c2y=0.951056516295153572f;
    const float2 w1 = make_float2( c1x,  c1y);
    const float2 w2 = make_float2( c2x,  c2y);
    const float2 w3 = make_float2(-c2x,  c2y);
    const float2 w4 = make_float2(-c1x,  c1y);
    for (int blk = threadIdx.x; blk < cnt10; blk += THR) {
        int o = 10*blk;
        float2 z[10];
        #pragma unroll
        for (int i=0;i<10;i++){
            float2 v = Xb[idx[o+i]];
            float  w = wt[o+i];
            z[i] = make_float2(v.x*w, v.y*w);
        }
        float2 E0=z[0], E1=z[2], E2=z[4], E3=z[6], E4=z[8];
        float2 O0=z[1], O1=z[3], O2=z[5], O3=z[7], O4=z[9];
        dft5<1>(E0,E1,E2,E3,E4);
        dft5<1>(O0,O1,O2,O3,O4);
        O1=cmul(O1,w1); O2=cmul(O2,w2); O3=cmul(O3,w3); O4=cmul(O4,w4);
        buf[o  ]=cadd(E0,O0); buf[o+5]=csub(E0,O0);
        buf[o+1]=cadd(E1,O1); buf[o+6]=csub(E1,O1);
        buf[o+2]=cadd(E2,O2); buf[o+7]=csub(E2,O2);
        buf[o+3]=cadd(E3,O3); buf[o+8]=csub(E3,O3);
        buf[o+4]=cadd(E4,O4); buf[o+9]=csub(E4,O4);
    }
    __syncthreads();
}

// generic inverse radix-10 stage; if ABS, writes |z| to U instead of buf
template<int M, int CC, int THR, bool ABS>
__device__ void s10i(float2* buf, float* U, int cnt, const float2* rtA, const float2* rtB){
    const float c1x=0.809016994374947424f, c1y=0.587785252292473129f;
    const float c2x=0.309016994374947424f, c2y=0.951056516295153572f;
    const float2 w10_1 = make_float2( c1x,  c1y);
    const float2 w10_2 = make_float2( c2x,  c2y);
    const float2 w10_3 = make_float2(-c2x,  c2y);
    const float2 w10_4 = make_float2(-c1x,  c1y);
    for (int idx = threadIdx.x; idx < cnt; idx += THR) {
        int blk = idx / M;
        int p   = idx - blk*M;
        int o   = blk*(10*M) + p;
        float2 z[10];
        #pragma unroll
        for (int i=0;i<10;i++) z[i] = buf[o + M*i];
        float2 v = twb(CC*p, rtA, rtB);
        v.y = -v.y;
        float2 b  = cmul(v,v);
        float2 b2 = cmul(b,b);
        float2 b3 = cmul(b2,b);
        float2 b4 = cmul(b2,b2);
        float2 m1 = cmul(w10_1, v);
        float2 m2 = cmul(w10_2, v);
        float2 m3 = cmul(w10_3, v);
        float2 m4 = cmul(w10_4, v);
        float2 E0=z[0], E1=cmul(z[2],b), E2=cmul(z[4],b2), E3=cmul(z[6],b3), E4=cmul(z[8],b4);
        float2 O0=z[1], O1=cmul(z[3],b), O2=cmul(z[5],b2), O3=cmul(z[7],b3), O4=cmul(z[9],b4);
        dft5<1>(E0,E1,E2,E3,E4);
        dft5<1>(O0,O1,O2,O3,O4);
        O0=cmul(O0,v ); O1=cmul(O1,m1); O2=cmul(O2,m2); O3=cmul(O3,m3); O4=cmul(O4,m4);
        float2 y[10];
        y[0]=cadd(E0,O0); y[5]=csub(E0,O0);
        y[1]=cadd(E1,O1); y[6]=csub(E1,O1);
        y[2]=cadd(E2,O2); y[7]=csub(E2,O2);
        y[3]=cadd(E3,O3); y[8]=csub(E3,O3);
        y[4]=cadd(E4,O4); y[9]=csub(E4,O4);
        if (ABS) {
            #pragma unroll
            for (int i=0;i<10;i++) U[o + M*i] = sqrtf(y[i].x*y[i].x + y[i].y*y[i].y);
        } else {
            #pragma unroll
            for (int i=0;i<10;i++) buf[o + M*i] = y[i];
        }
    }
    __syncthreads();
}

// inverse radix-4 stage, M=1000, sub-length 4000 (twiddle = conj W_16000^{4p s})
template<int THR, bool ABS>
__device__ void s4i(float2* buf, float* U, int cnt, const float2* rtA, const float2* rtB){
    for (int idx = threadIdx.x; idx < cnt; idx += THR) {
        int blk = idx / 1000;
        int p   = idx - blk*1000;
        int o   = blk*4000 + p;
        float2 z0=buf[o], z1=buf[o+1000], z2=buf[o+2000], z3=buf[o+3000];
        float2 w1 = twb(4*p, rtA, rtB); w1.y = -w1.y;
        float2 w2 = cmul(w1,w1), w3 = cmul(w2,w1);
        z1=cmul(z1,w1); z2=cmul(z2,w2); z3=cmul(z3,w3);
        dft4<1>(z0,z1,z2,z3);
        if (ABS) {
            U[o]      = sqrtf(z0.x*z0.x + z0.y*z0.y);
            U[o+1000] = sqrtf(z1.x*z1.x + z1.y*z1.y);
            U[o+2000] = sqrtf(z2.x*z2.x + z2.y*z2.y);
            U[o+3000] = sqrtf(z3.x*z3.x + z3.y*z3.y);
        } else {
            buf[o]=z0; buf[o+1000]=z1; buf[o+2000]=z2; buf[o+3000]=z3;
        }
    }
    __syncthreads();
}

// inverse radix-2 stage, half-offset M2, twiddle conj W_16000^{DD p}
template<int THR, int M2, int DD>
__device__ void s2i_abs(float2* buf, float* U, const float2* rtA, const float2* rtB){
    for (int p = threadIdx.x; p < M2; p += THR) {
        float2 a = buf[p];
        float2 w = twb(DD*p, rtA, rtB); w.y = -w.y;
        float2 bb = cmul(buf[p+M2], w);
        float2 y0 = cadd(a,bb), y1 = csub(a,bb);
        U[p]    = sqrtf(y0.x*y0.x + y0.y*y0.y);
        U[p+M2] = sqrtf(y1.x*y1.x + y1.y*y1.y);
    }
    __syncthreads();
}

// class-A last stage: fused inverse radix-16 with abs (size 16000 only)
template<int THR>
__device__ void stage16_inv_abs(const float2* buf, float* U, const float2* rtA, const float2* rtB){
    const float2 c16_1 = make_float2(0.92387953251128674f,  0.38268343236508977f);
    const float2 c16_2 = make_float2(0.70710678118654752f,  0.70710678118654752f);
    const float2 c16_3 = make_float2(0.38268343236508977f,  0.92387953251128674f);
    for (int p = threadIdx.x; p < 1000; p += THR) {
        float2 z[16];
        #pragma unroll
        for (int s1=0;s1<4;s1++)
            #pragma unroll
            for (int s2=0;s2<4;s2++)
                z[4*s2+s1] = buf[s1*4000 + s2*1000 + p];
        float2 a = twb(p, rtA, rtB);   a.y = -a.y;
        float2 b = twb(4*p, rtA, rtB); b.y = -b.y;
        float2 b2 = cmul(b,b), b3 = cmul(b2,b);
        #pragma unroll
        for (int s1=0;s1<4;s1++){ z[4+s1]=cmul(z[4+s1],b); z[8+s1]=cmul(z[8+s1],b2); z[12+s1]=cmul(z[12+s1],b3); }
        #pragma unroll
        for (int s1=0;s1<4;s1++) dft4<1>(z[s1], z[4+s1], z[8+s1], z[12+s1]);
        #pragma unroll
        for (int j=0;j<4;j++){
            float2 t = (j==0)? a : (j==1? cmul(a,c16_1) : (j==2? cmul(a,c16_2) : cmul(a,c16_3)));
            float2 t2 = cmul(t,t);
            z[4*j+1]=cmul(z[4*j+1],t); z[4*j+2]=cmul(z[4*j+2],t2); z[4*j+3]=cmul(z[4*j+3],cmul(t2,t));
        }
        #pragma unroll
        for (int j=0;j<4;j++) dft4<1>(z[4*j+0], z[4*j+1], z[4*j+2], z[4*j+3]);
        #pragma unroll
        for (int j=0;j<4;j++)
            #pragma unroll
            for (int i=0;i<4;i++){
                float2 v = z[4*j+i];
                U[p + 1000*j + 4000*i] = sqrtf(v.x*v.x + v.y*v.y);
            }
    }
    __syncthreads();
}

// ================= shared small helpers =================
template<int THR>
__device__ void init_tables(float2* rtA, float2* rtB, float* sphi){
    for (int i = threadIdx.x; i < 128; i += THR) rtA[i] = d_rtA[i];
    for (int i = threadIdx.x; i < 125; i += THR) rtB[i] = d_rtB[i];
    for (int i = threadIdx.x; i < NTAPS; i += THR) sphi[i] = d_phiw[i];
}

// decimated smoothing: S1[m] = DEC * sum_i phi(DEC*i) * U[(64m/DEC - i) mod NJ]
template<int NJ, int DEC, int THR>
__device__ void smooth_dec(const float* __restrict__ S, const float* __restrict__ sphi, float* dst){
    const int T = 128 / DEC;
    const int ITER = (2*T + 1 + 31) / 32;
    int w = threadIdx.x >> 5, l = threadIdx.x & 31;
    for (int m0 = w; m0 < NOUT; m0 += THR/32) {
        int tau = (64/DEC) * m0;
        float acc = 0.f;
        #pragma unroll
        for (int it = 0; it < ITER; ++it) {
            int tl = l + 32*it;
            if (tl <= 2*T) {
                int i = tl - T;
                int id = tau - i;
                if (id >= NJ) id -= NJ;
                if (id < 0)   id += NJ;
                acc += sphi[DEC*i + 128] * S[id];
            }
        }
        #pragma unroll
        for (int o = 16; o; o >>= 1) acc += __shfl_down_sync(0xffffffffu, acc, o);
        if (l == 0) dst[m0] = acc * (float)DEC;
    }
}

// ---------------- kernel 1: forward FFT of x (+ S0) ----------------
__global__ __launch_bounds__(NT, 1) void k_fwd(const float* __restrict__ x){
    extern __shared__ __align__(16) unsigned char sm[];
    float2* buf = (float2*)sm;
    float*  xs  = (float*)(sm + TN*sizeof(float2));
    __shared__ float2 rtA[128]; __shared__ float2 rtB[125]; __shared__ float sphi[NTAPS];
    int b = blockIdx.x;
    init_tables<NT>(rtA, rtB, sphi);
    const float4* xb4 = (const float4*)(x + b*TN);
    float4* xs4 = (float4*)xs;
    for (int n = threadIdx.x; n < TN/4; n += NT) xs4[n] = xb4[n];
    __syncthreads();
    smooth_dec<TN,1,NT>(xs, sphi, &d_S1[(b*NCH + 0)*NOUT]);
    stage16_fwd(buf, xs, rtA, rtB);
    stage10_fwd<100,16>(buf, rtA, rtB);
    stage10_fwd<10,160>(buf, rtA, rtB);
    stage10_fwd_store(buf, d_X + b*TN);
}

// ---------------- kernel 2: per-class band-pass ifft + |.| + smoothing ----------------
// CLS: 0=A(16000,D1) 1=B(8000,D2) 2=C(4000,D4) 3=D(2000,D8) 4=E(1000,D16)
template<int NJ, int DEC, int THR, int CLS>
__global__ __launch_bounds__(THR, 1) void k_bandT(int j0, int off0){
    extern __shared__ __align__(16) unsigned char sm[];
    float2* buf = (float2*)sm;
    float*  U   = (float*)(sm + NJ*sizeof(float2));
    __shared__ float2 rtA[128]; __shared__ float2 rtB[125]; __shared__ float sphi[NTAPS];
    int jc = blockIdx.x, b = blockIdx.y;
    int j = j0 + jc;
    init_tables<THR>(rtA, rtB, sphi);
    __syncthreads();
    const float2* Xb = d_X + b*TN;
    const int*   idx = d_idx + off0 + jc*NJ;
    const float* wt  = d_wt  + off0 + jc*NJ;
    s10_load<THR>(buf, Xb, idx, wt, NJ/10);
    s10i<10,160,THR,false>(buf, U, NJ/10, rtA, rtB);
    if (CLS == 4) {
        s10i<100,16,THR,true>(buf, U, NJ/10, rtA, rtB);
    } else {
        s10i<100,16,THR,false>(buf, U, NJ/10, rtA, rtB);
        if (CLS == 0) stage16_inv_abs<THR>(buf, U, rtA, rtB);
        if (CLS == 1) { s4i<THR,false>(buf, U, 2000, rtA, rtB); s2i_abs<THR,4000,2>(buf, U, rtA, rtB); }
        if (CLS == 2) s4i<THR,true>(buf, U, 1000, rtA, rtB);
        if (CLS == 3) s2i_abs<THR,1000,8>(buf, U, rtA, rtB);
    }
    smooth_dec<NJ,DEC,THR>(U, sphi, &d_S1[(b*NCH + 1 + j)*NOUT]);
}

// ---------------- kernel 3: channel-group means ----------------
__global__ void k_reduce(float* __restrict__ out){
    int i = blockIdx.x * blockDim.x + threadIdx.x;
    if (i >= NB*3*NOUT) return;
    int m0 = i % NOUT;
    int g  = (i / NOUT) % 3;
    int b  = i / (3*NOUT);
    int c0 = (g==0) ? 0 : (g==1 ? 12 : 24);
    int nc = (g==2) ? 13 : 12;
    float acc = 0.f;
    for (int c = 0; c < nc; ++c) acc += d_S1[(b*NCH + c0 + c)*NOUT + m0];
    out[i] = acc / (float)nc;
}

// ---------------- launch ----------------
extern "C" void kernel_launch(void* const* d_in, const int* in_sizes, int n_in,
                              void* d_out, int out_size) {
    (void)in_sizes; (void)n_in; (void)out_size;
    const float* x = (const float*)d_in[0];
    float* out = (float*)d_out;
    const int smF = TN*8 + TN*4;            // k_fwd: 192000
    const int smA = 16000*8 + 16000*4;      // 192000
    const int smB = 8000*8  + 8000*4;       // 96000
    const int smC = 4000*8  + 4000*4;       // 48000
    const int smD = 2000*8  + 2000*4;       // 24000
    const int smE = 1000*8  + 1000*4;       // 12000
    cudaFuncSetAttribute(k_fwd, cudaFuncAttributeMaxDynamicSharedMemorySize, smF);
    cudaFuncSetAttribute(k_bandT<16000,1,1024,0>, cudaFuncAttributeMaxDynamicSharedMemorySize, smA);
    cudaFuncSetAttribute(k_bandT<8000,2,1024,1>,  cudaFuncAttributeMaxDynamicSharedMemorySize, smB);
    cudaFuncSetAttribute(k_bandT<4000,4,512,2>,   cudaFuncAttributeMaxDynamicSharedMemorySize, smC);
    cudaFuncSetAttribute(k_bandT<2000,8,256,3>,   cudaFuncAttributeMaxDynamicSharedMemorySize, smD);
    cudaFuncSetAttribute(k_bandT<1000,16,128,4>,  cudaFuncAttributeMaxDynamicSharedMemorySize, smE);
    prep_phi<<<NTAPS, 32>>>();
    prep_tw<<<1, 128>>>();
    prep_band<<<dim3(63, NF), 256>>>();
    k_fwd<<<NB, NT, smF>>>(x);
    k_bandT<16000,1,1024,0><<<dim3(2,  NB), 1024, smA>>>(0,  0);
    k_bandT<8000,2,1024,1> <<<dim3(7,  NB), 1024, smB>>>(2,  32000);
    k_bandT<4000,4,512,2>  <<<dim3(7,  NB), 512,  smC>>>(9,  88000);
    k_bandT<2000,8,256,3>  <<<dim3(10, NB), 256,  smD>>>(16, 116000);
    k_bandT<1000,16,128,4> <<<dim3(10, NB), 128,  smE>>>(26, 136000);
    k_reduce<<<(NB*3*NOUT + 255)/256, 256>>>(out);
}